// round 1
// baseline (speedup 1.0000x reference)
#include <cuda_runtime.h>

// ChamferDistanceLoss: B=8, N=M=4096, D=3.
// loss = mean_b( sum_{valid n} min_m d2(fg_n, prj_m) / n_valid
//              + mean_m min_{valid n} d2(fg_n, prj_m) )
// PAD rows (coords == 10000) are ~3e8 away from any valid point, so they never
// win a min; validity for the x->y mean is recomputed from fg.x != PAD.

#define PADV 10000.0f
#define TPB  256
#define TILE 512

// scratch: per-point running mins as uint bits (d2 >= 0 so uint order == float order)
static __device__ unsigned int g_minq[65536];  // fg -> prj mins, [B*N]
static __device__ unsigned int g_minr[65536];  // prj -> fg mins, [B*M]

__global__ void init_kernel(float* out, int tot) {
    int i = blockIdx.x * blockDim.x + threadIdx.x;
    if (i == 0) out[0] = 0.0f;
    if (i < tot) { g_minq[i] = 0x7F7FFFFFu; g_minr[i] = 0x7F7FFFFFu; }
}

// Generic direction kernel: for each query point, min squared distance to all
// reference points. Grid: (ceil(Nq/TPB), B, SPLIT). Each z-slice handles a
// contiguous chunk of the reference set; partial mins merged with atomicMin.
__global__ void nn_min_kernel(const float* __restrict__ q,
                              const float* __restrict__ r,
                              int sel, int Nq, int Nr) {
    __shared__ float4 tile[TILE];
    unsigned int* outmin = sel ? g_minr : g_minq;

    int b  = blockIdx.y;
    int nq = blockIdx.x * TPB + threadIdx.x;
    bool active = nq < Nq;
    float ax = 0.f, ay = 0.f, az = 0.f;
    if (active) {
        const float* qp = q + ((size_t)b * Nq + nq) * 3;
        ax = qp[0]; ay = qp[1]; az = qp[2];
    }

    int len = (Nr + gridDim.z - 1) / gridDim.z;
    int r0  = blockIdx.z * len;
    int r1  = r0 + len; if (r1 > Nr) r1 = Nr;
    const float* rb = r + (size_t)b * Nr * 3;

    float best = 3.0e38f;
    for (int base = r0; base < r1; base += TILE) {
        int cnt = r1 - base; if (cnt > TILE) cnt = TILE;
        __syncthreads();  // protect tile from previous iteration's readers
        for (int j = threadIdx.x; j < cnt; j += TPB) {
            const float* pp = rb + (size_t)(base + j) * 3;
            tile[j] = make_float4(pp[0], pp[1], pp[2], 0.f);
        }
        __syncthreads();
        if (cnt == TILE) {
            #pragma unroll 8
            for (int j = 0; j < TILE; j++) {
                float4 p = tile[j];
                float dx = ax - p.x, dy = ay - p.y, dz = az - p.z;
                float d  = fmaf(dx, dx, fmaf(dy, dy, dz * dz));
                best = fminf(best, d);
            }
        } else {
            for (int j = 0; j < cnt; j++) {
                float4 p = tile[j];
                float dx = ax - p.x, dy = ay - p.y, dz = az - p.z;
                float d  = fmaf(dx, dx, fmaf(dy, dy, dz * dz));
                best = fminf(best, d);
            }
        }
    }
    if (active) atomicMin(&outmin[(size_t)b * Nq + nq], __float_as_uint(best));
}

// Per-batch reduction: cham_x = sum(valid mins)/n_valid, cham_y = mean over M.
// Each block handles one batch sample; 8 atomicAdds into the scalar output.
__global__ void reduce_kernel(const float* __restrict__ fg, float* out,
                              int B, int N, int M) {
    __shared__ float sh[TPB * 3];
    int b = blockIdx.x;
    float sx = 0.f, sy = 0.f, cv = 0.f;
    for (int n = threadIdx.x; n < N; n += TPB) {
        if (fg[((size_t)b * N + n) * 3] != PADV) {
            sx += __uint_as_float(g_minq[b * N + n]);
            cv += 1.0f;
        }
    }
    for (int m = threadIdx.x; m < M; m += TPB)
        sy += __uint_as_float(g_minr[b * M + m]);

    sh[threadIdx.x]           = sx;
    sh[TPB + threadIdx.x]     = sy;
    sh[2 * TPB + threadIdx.x] = cv;
    __syncthreads();
    for (int s = TPB / 2; s > 0; s >>= 1) {
        if (threadIdx.x < s) {
            sh[threadIdx.x]           += sh[threadIdx.x + s];
            sh[TPB + threadIdx.x]     += sh[TPB + threadIdx.x + s];
            sh[2 * TPB + threadIdx.x] += sh[2 * TPB + threadIdx.x + s];
        }
        __syncthreads();
    }
    if (threadIdx.x == 0) {
        float val = sh[0] / sh[2 * TPB] + sh[TPB] / (float)M;
        atomicAdd(out, val / (float)B);
    }
}

extern "C" void kernel_launch(void* const* d_in, const int* in_sizes, int n_in,
                              void* d_out, int out_size) {
    const float* fg  = (const float*)d_in[0];
    const float* prj = (const float*)d_in[1];
    int B = in_sizes[2];
    int N = in_sizes[0] / (3 * B);
    int M = in_sizes[1] / (3 * B);
    float* out = (float*)d_out;

    int maxNM = (N > M) ? N : M;
    int tot = B * maxNM;
    init_kernel<<<(tot + TPB - 1) / TPB, TPB>>>(out, tot);

    dim3 ga((N + TPB - 1) / TPB, B, 4);
    nn_min_kernel<<<ga, TPB>>>(fg, prj, 0, N, M);   // x -> y
    dim3 gb((M + TPB - 1) / TPB, B, 4);
    nn_min_kernel<<<gb, TPB>>>(prj, fg, 1, M, N);   // y -> x

    reduce_kernel<<<B, TPB>>>(fg, out, B, N, M);
}

// round 2
// speedup vs baseline: 2.8910x; 2.8910x over previous
#include <cuda_runtime.h>

// ChamferDistanceLoss: B=8, N=M=4096, D=3.
// d2(q,p) = ||q||^2 + ||p||^2 - 2 q.p  (same expansion the reference uses).
// Inner loop: per tile point, packed f32x2 FFMA chain evaluates d' = ||p||^2 - 2 q.p
// for 2 queries at once; ||q||^2 added once per query after the min.
// PAD rows (coords == 10000) are ~3e8 from any valid point -> never win a min.

#define PADV  10000.0f
#define TPB   256
#define QPT   8            // queries per thread (4 packed f32x2 pairs)
#define QPB   (TPB * QPT)  // 2048 queries per block
#define SPLIT 8
#define TILE  256
#define MAXB  8
#define MAXQ  4096
#define RCHUNK 4

// per-(dir,split,b,query) partial mins -- private slots, no atomics, no init
static __device__ float g_pmin[2][SPLIT][MAXB][MAXQ];
// per-(dir,b,chunk) partial sums from reduce blocks
static __device__ float g_rsum[2][MAXB][RCHUNK];
static __device__ float g_rcnt[MAXB][RCHUNK];

__device__ __forceinline__ unsigned long long ffma2(unsigned long long a,
                                                    unsigned long long b,
                                                    unsigned long long c) {
    unsigned long long d;
    asm("fma.rn.f32x2 %0, %1, %2, %3;" : "=l"(d) : "l"(a), "l"(b), "l"(c));
    return d;
}
__device__ __forceinline__ unsigned long long pack2(float lo, float hi) {
    unsigned long long d;
    asm("mov.b64 %0, {%1, %2};" : "=l"(d) : "f"(lo), "f"(hi));
    return d;
}
__device__ __forceinline__ void unpack2(unsigned long long v, float& lo, float& hi) {
    asm("mov.b64 {%0, %1}, %2;" : "=f"(lo), "=f"(hi) : "l"(v));
}

// grid: (ceil(maxQ/QPB), B, 2*SPLIT). z encodes direction + reference slice.
__global__ __launch_bounds__(TPB) void nn_kernel(const float* __restrict__ fg,
                                                 const float* __restrict__ prj,
                                                 int N, int M) {
    __shared__ __align__(16) unsigned long long s_tile[TILE][4];

    int dir = (blockIdx.z >= SPLIT) ? 1 : 0;
    int zs  = blockIdx.z - dir * SPLIT;
    int b   = blockIdx.y;
    const float* q = dir ? prj : fg;
    const float* r = dir ? fg  : prj;
    int Nq = dir ? M : N;
    int Nr = dir ? N : M;
    if (blockIdx.x * QPB >= Nq) return;

    // load 8 queries per thread, pack into 4 f32x2 pairs
    float qx[QPT], qy[QPT], qz[QPT], qn[QPT];
    int q0 = blockIdx.x * QPB + threadIdx.x;
    #pragma unroll
    for (int k = 0; k < QPT; k++) {
        int qi = q0 + k * TPB;
        int qc = (qi < Nq) ? qi : 0;
        const float* p = q + ((size_t)b * Nq + qc) * 3;
        qx[k] = p[0]; qy[k] = p[1]; qz[k] = p[2];
        qn[k] = qx[k]*qx[k] + qy[k]*qy[k] + qz[k]*qz[k];
    }
    unsigned long long ax[4], ay[4], az[4];
    #pragma unroll
    for (int j = 0; j < 4; j++) {
        ax[j] = pack2(qx[2*j], qx[2*j+1]);
        ay[j] = pack2(qy[2*j], qy[2*j+1]);
        az[j] = pack2(qz[2*j], qz[2*j+1]);
    }

    float best[QPT];
    #pragma unroll
    for (int k = 0; k < QPT; k++) best[k] = 3.0e38f;

    int len = (Nr + SPLIT - 1) / SPLIT;
    int r0  = zs * len;
    int r1  = min(r0 + len, Nr);
    const float* rb = r + (size_t)b * Nr * 3;

    for (int base = r0; base < r1; base += TILE) {
        int cnt = min(TILE, r1 - base);
        __syncthreads();
        for (int j = threadIdx.x; j < cnt; j += TPB) {
            const float* pp = rb + (size_t)(base + j) * 3;
            float px = pp[0], py = pp[1], pz = pp[2];
            float w = px*px + py*py + pz*pz;
            s_tile[j][0] = pack2(-2.f*px, -2.f*px);
            s_tile[j][1] = pack2(-2.f*py, -2.f*py);
            s_tile[j][2] = pack2(-2.f*pz, -2.f*pz);
            s_tile[j][3] = pack2(w, w);
        }
        __syncthreads();
        #pragma unroll 4
        for (int j = 0; j < cnt; j++) {
            ulonglong2 t01 = *reinterpret_cast<const ulonglong2*>(&s_tile[j][0]);
            ulonglong2 t23 = *reinterpret_cast<const ulonglong2*>(&s_tile[j][2]);
            #pragma unroll
            for (int p2 = 0; p2 < 4; p2++) {
                unsigned long long d = ffma2(t23.x, az[p2], t23.y);
                d = ffma2(t01.y, ay[p2], d);
                d = ffma2(t01.x, ax[p2], d);
                float lo, hi;
                unpack2(d, lo, hi);
                best[2*p2]     = fminf(best[2*p2],     lo);
                best[2*p2 + 1] = fminf(best[2*p2 + 1], hi);
            }
        }
    }
    #pragma unroll
    for (int k = 0; k < QPT; k++) {
        int qi = q0 + k * TPB;
        if (qi < Nq) g_pmin[dir][zs][b][qi] = best[k] + qn[k];
    }
}

// grid: (RCHUNK, B, 2). Combines split partials, applies validity + clamp,
// writes per-(dir,b,chunk) partial sums (private slots, no atomics).
__global__ __launch_bounds__(TPB) void reduce_kernel(const float* __restrict__ fg,
                                                     int N, int M) {
    int chunk = blockIdx.x, b = blockIdx.y, dir = blockIdx.z;
    int Nq  = dir ? M : N;
    int per = (Nq + RCHUNK - 1) / RCHUNK;
    int qs  = chunk * per;
    int qe  = min(qs + per, Nq);

    float sum = 0.f, cntv = 0.f;
    for (int qi = qs + threadIdx.x; qi < qe; qi += TPB) {
        float m = g_pmin[dir][0][b][qi];
        #pragma unroll
        for (int s = 1; s < SPLIT; s++) m = fminf(m, g_pmin[dir][s][b][qi]);
        m = fmaxf(m, 0.f);
        if (dir == 0) {
            if (fg[((size_t)b * N + qi) * 3] != PADV) { sum += m; cntv += 1.f; }
        } else {
            sum += m;
        }
    }
    // warp reduce, then cross-warp via shared
    #pragma unroll
    for (int o = 16; o > 0; o >>= 1) {
        sum  += __shfl_xor_sync(0xFFFFFFFFu, sum,  o);
        cntv += __shfl_xor_sync(0xFFFFFFFFu, cntv, o);
    }
    __shared__ float ws[TPB / 32][2];
    int wid = threadIdx.x / 32, lane = threadIdx.x % 32;
    if (lane == 0) { ws[wid][0] = sum; ws[wid][1] = cntv; }
    __syncthreads();
    if (threadIdx.x == 0) {
        float ts = 0.f, tc = 0.f;
        for (int w = 0; w < TPB / 32; w++) { ts += ws[w][0]; tc += ws[w][1]; }
        g_rsum[dir][b][chunk] = ts;
        if (dir == 0) g_rcnt[b][chunk] = tc;
    }
}

__global__ void final_kernel(float* out, int M, int B) {
    float v = 0.f;
    if (threadIdx.x < B) {
        int b = threadIdx.x;
        float sx = 0.f, sy = 0.f, c = 0.f;
        #pragma unroll
        for (int ch = 0; ch < RCHUNK; ch++) {
            sx += g_rsum[0][b][ch];
            sy += g_rsum[1][b][ch];
            c  += g_rcnt[b][ch];
        }
        v = sx / c + sy / (float)M;
    }
    #pragma unroll
    for (int o = 16; o > 0; o >>= 1) v += __shfl_xor_sync(0xFFFFFFFFu, v, o);
    if (threadIdx.x == 0) out[0] = v / (float)B;
}

extern "C" void kernel_launch(void* const* d_in, const int* in_sizes, int n_in,
                              void* d_out, int out_size) {
    const float* fg  = (const float*)d_in[0];
    const float* prj = (const float*)d_in[1];
    int B = in_sizes[2];
    int N = in_sizes[0] / (3 * B);
    int M = in_sizes[1] / (3 * B);
    float* out = (float*)d_out;

    int maxq = (N > M) ? N : M;
    int nqb  = (maxq + QPB - 1) / QPB;
    dim3 g(nqb, B, 2 * SPLIT);
    nn_kernel<<<g, TPB>>>(fg, prj, N, M);
    reduce_kernel<<<dim3(RCHUNK, B, 2), TPB>>>(fg, N, M);
    final_kernel<<<1, 32>>>(out, M, B);
}

// round 3
// speedup vs baseline: 3.1004x; 1.0724x over previous
#include <cuda_runtime.h>

// ChamferDistanceLoss: B=8, N=M=4096, D=3.
// d2(q,p) = ||q||^2 + (||p||^2 - 2 q.p); inner chain is 3 packed FFMA2 per
// 2 queries per point, scalar FMNMX per query. Issue-slot-bound: this round
// raises occupancy (1024 blocks x 128thr) so issue% -> ~85.

#define PADV  10000.0f
#define TPB   128
#define QPT   8            // queries per thread (4 packed f32x2 pairs)
#define QPB   (TPB * QPT)  // 1024 queries per block
#define SPLIT 16
#define TILE  256
#define MAXB  8
#define MAXQ  4096
#define RCHUNK 4

static __device__ float g_pmin[2][SPLIT][MAXB][MAXQ];   // partial mins, private slots
static __device__ float g_rsum[2][MAXB][RCHUNK];
static __device__ float g_rcnt[MAXB][RCHUNK];

__device__ __forceinline__ unsigned long long ffma2(unsigned long long a,
                                                    unsigned long long b,
                                                    unsigned long long c) {
    unsigned long long d;
    asm("fma.rn.f32x2 %0, %1, %2, %3;" : "=l"(d) : "l"(a), "l"(b), "l"(c));
    return d;
}
__device__ __forceinline__ unsigned long long pack2(float lo, float hi) {
    unsigned long long d;
    asm("mov.b64 %0, {%1, %2};" : "=l"(d) : "f"(lo), "f"(hi));
    return d;
}
__device__ __forceinline__ void unpack2(unsigned long long v, float& lo, float& hi) {
    asm("mov.b64 {%0, %1}, %2;" : "=f"(lo), "=f"(hi) : "l"(v));
}

// grid: (ceil(maxQ/QPB), B, 2*SPLIT). z encodes direction + reference slice.
__global__ __launch_bounds__(TPB) void nn_kernel(const float* __restrict__ fg,
                                                 const float* __restrict__ prj,
                                                 int N, int M) {
    __shared__ __align__(16) unsigned long long s_tile[TILE][4];

    int dir = (blockIdx.z >= SPLIT) ? 1 : 0;
    int zs  = blockIdx.z - dir * SPLIT;
    int b   = blockIdx.y;
    const float* q = dir ? prj : fg;
    const float* r = dir ? fg  : prj;
    int Nq = dir ? M : N;
    int Nr = dir ? N : M;
    if (blockIdx.x * QPB >= Nq) return;

    // load 8 queries per thread, pack into 4 f32x2 pairs
    float qx[QPT], qy[QPT], qz[QPT], qn[QPT];
    int q0 = blockIdx.x * QPB + threadIdx.x;
    #pragma unroll
    for (int k = 0; k < QPT; k++) {
        int qi = q0 + k * TPB;
        int qc = (qi < Nq) ? qi : 0;
        const float* p = q + ((size_t)b * Nq + qc) * 3;
        qx[k] = p[0]; qy[k] = p[1]; qz[k] = p[2];
        qn[k] = qx[k]*qx[k] + qy[k]*qy[k] + qz[k]*qz[k];
    }
    unsigned long long ax[4], ay[4], az[4];
    #pragma unroll
    for (int j = 0; j < 4; j++) {
        ax[j] = pack2(qx[2*j], qx[2*j+1]);
        ay[j] = pack2(qy[2*j], qy[2*j+1]);
        az[j] = pack2(qz[2*j], qz[2*j+1]);
    }

    float best[QPT];
    #pragma unroll
    for (int k = 0; k < QPT; k++) best[k] = 3.0e38f;

    int len = (Nr + SPLIT - 1) / SPLIT;
    int r0  = zs * len;
    int r1  = min(r0 + len, Nr);
    const float* rb = r + (size_t)b * Nr * 3;

    for (int base = r0; base < r1; base += TILE) {
        int cnt = min(TILE, r1 - base);
        __syncthreads();
        for (int j = threadIdx.x; j < cnt; j += TPB) {
            const float* pp = rb + (size_t)(base + j) * 3;
            float px = pp[0], py = pp[1], pz = pp[2];
            float w = px*px + py*py + pz*pz;
            s_tile[j][0] = pack2(-2.f*px, -2.f*px);
            s_tile[j][1] = pack2(-2.f*py, -2.f*py);
            s_tile[j][2] = pack2(-2.f*pz, -2.f*pz);
            s_tile[j][3] = pack2(w, w);
        }
        __syncthreads();
        #pragma unroll 8
        for (int j = 0; j < cnt; j++) {
            ulonglong2 t01 = *reinterpret_cast<const ulonglong2*>(&s_tile[j][0]);
            ulonglong2 t23 = *reinterpret_cast<const ulonglong2*>(&s_tile[j][2]);
            #pragma unroll
            for (int p2 = 0; p2 < 4; p2++) {
                unsigned long long d = ffma2(t23.x, az[p2], t23.y);
                d = ffma2(t01.y, ay[p2], d);
                d = ffma2(t01.x, ax[p2], d);
                float lo, hi;
                unpack2(d, lo, hi);
                best[2*p2]     = fminf(best[2*p2],     lo);
                best[2*p2 + 1] = fminf(best[2*p2 + 1], hi);
            }
        }
    }
    #pragma unroll
    for (int k = 0; k < QPT; k++) {
        int qi = q0 + k * TPB;
        if (qi < Nq) g_pmin[dir][zs][b][qi] = best[k] + qn[k];
    }
}

// grid: (RCHUNK, B, 2). Combine split partials, apply validity + clamp,
// write per-(dir,b,chunk) partial sums (private slots, no atomics).
__global__ __launch_bounds__(256) void reduce_kernel(const float* __restrict__ fg,
                                                     int N, int M) {
    const int RT = 256;
    int chunk = blockIdx.x, b = blockIdx.y, dir = blockIdx.z;
    int Nq  = dir ? M : N;
    int per = (Nq + RCHUNK - 1) / RCHUNK;
    int qs  = chunk * per;
    int qe  = min(qs + per, Nq);

    float sum = 0.f, cntv = 0.f;
    for (int qi = qs + threadIdx.x; qi < qe; qi += RT) {
        float m = g_pmin[dir][0][b][qi];
        #pragma unroll
        for (int s = 1; s < SPLIT; s++) m = fminf(m, g_pmin[dir][s][b][qi]);
        m = fmaxf(m, 0.f);
        if (dir == 0) {
            if (fg[((size_t)b * N + qi) * 3] != PADV) { sum += m; cntv += 1.f; }
        } else {
            sum += m;
        }
    }
    #pragma unroll
    for (int o = 16; o > 0; o >>= 1) {
        sum  += __shfl_xor_sync(0xFFFFFFFFu, sum,  o);
        cntv += __shfl_xor_sync(0xFFFFFFFFu, cntv, o);
    }
    __shared__ float ws[RT / 32][2];
    int wid = threadIdx.x / 32, lane = threadIdx.x % 32;
    if (lane == 0) { ws[wid][0] = sum; ws[wid][1] = cntv; }
    __syncthreads();
    if (threadIdx.x == 0) {
        float ts = 0.f, tc = 0.f;
        for (int w = 0; w < RT / 32; w++) { ts += ws[w][0]; tc += ws[w][1]; }
        g_rsum[dir][b][chunk] = ts;
        if (dir == 0) g_rcnt[b][chunk] = tc;
    }
}

__global__ void final_kernel(float* out, int M, int B) {
    float v = 0.f;
    if (threadIdx.x < B) {
        int b = threadIdx.x;
        float sx = 0.f, sy = 0.f, c = 0.f;
        #pragma unroll
        for (int ch = 0; ch < RCHUNK; ch++) {
            sx += g_rsum[0][b][ch];
            sy += g_rsum[1][b][ch];
            c  += g_rcnt[b][ch];
        }
        v = sx / c + sy / (float)M;
    }
    #pragma unroll
    for (int o = 16; o > 0; o >>= 1) v += __shfl_xor_sync(0xFFFFFFFFu, v, o);
    if (threadIdx.x == 0) out[0] = v / (float)B;
}

extern "C" void kernel_launch(void* const* d_in, const int* in_sizes, int n_in,
                              void* d_out, int out_size) {
    const float* fg  = (const float*)d_in[0];
    const float* prj = (const float*)d_in[1];
    int B = in_sizes[2];
    int N = in_sizes[0] / (3 * B);
    int M = in_sizes[1] / (3 * B);
    float* out = (float*)d_out;

    int maxq = (N > M) ? N : M;
    int nqb  = (maxq + QPB - 1) / QPB;
    dim3 g(nqb, B, 2 * SPLIT);
    nn_kernel<<<g, TPB>>>(fg, prj, N, M);
    reduce_kernel<<<dim3(RCHUNK, B, 2), 256>>>(fg, N, M);
    final_kernel<<<1, 32>>>(out, M, B);
}